// round 1
// baseline (speedup 1.0000x reference)
#include <cuda_runtime.h>

// ===================== problem constants =====================
#define TSEG 22
#define NBT  44            // B*T = 2*22
#define PIX  49            // 7*7

// ===================== scratch (static device memory) =====================
__device__ float g_xt[(size_t)NBT * 2048 * PIX];      // (bt, c, p)
__device__ float g_mx[(size_t)NBT * 2048 * PIX];      // masked x
__device__ float g_Gx[(size_t)NBT * 2048 * PIX];      // conv_x(mx_t) with lstm_w x-part
__device__ float g_y1[(size_t)NBT * 1024 * PIX];
__device__ float g_y2[(size_t)NBT * 512 * PIX];
__device__ float g_mask[NBT * PIX];
__device__ float g_meanx[2 * 2048 * PIX];
__device__ float g_mxc[NBT * 2048];
__device__ float g_attfea[NBT];
__device__ float g_aw[NBT];
__device__ float g_tmp1[2 * 1024 * PIX];
__device__ float g_h[2 * 512 * PIX];
__device__ float g_cst[2 * 512 * PIX];
__device__ float g_gates0[2 * 2048 * PIX];
__device__ float g_part[(size_t)8 * 2 * 2048 * PIX];  // ksplit partials
__device__ float g_houts[TSEG * 2 * 512];

// ===================== f32x2 helpers =====================
__device__ __forceinline__ void fma2(unsigned long long &d, unsigned long long a, unsigned long long b) {
    asm("fma.rn.f32x2 %0, %1, %2, %3;" : "=l"(d) : "l"(a), "l"(b), "l"(d));
}
__device__ __forceinline__ unsigned long long pack2(float x) {
    unsigned long long r;
    asm("mov.b64 %0, {%1, %1};" : "=l"(r) : "f"(x));
    return r;
}
__device__ __forceinline__ float2 unpack2(unsigned long long v) {
    float2 f;
    asm("mov.b64 {%0, %1}, %2;" : "=f"(f.x), "=f"(f.y) : "l"(v));
    return f;
}

// ===================== generic 3x3 SAME conv on 7x7, NCHW =====================
// grid: (N, OC/64, nsplit); block: (49, 8)
// in: (N, IC, 49)  wt: (OC, wstride, 3, 3) using ic range [ic0, ic0+IC/nsplit)
// nsplit==1: writes final (postop==1 -> BN+ReLU) at out[(n*OC+oc)*49+p]
// nsplit>1 : writes raw partial at out[((ks*N+n)*OC+oc)*49+p]
#define OCT 64
#define ICC 8
__global__ __launch_bounds__(392) void conv3x3_k(
    const float* __restrict__ in, const float* __restrict__ wt,
    const float* __restrict__ bn, float* __restrict__ out,
    int IC, int OC, int wstride, int nsplit, int postop)
{
    int n = blockIdx.x;
    int N = gridDim.x;
    int ocbase = blockIdx.y * OCT;
    int ks = blockIdx.z;
    int icn = IC / nsplit;
    int ic0 = ks * icn;
    int p = threadIdx.x;          // 0..48
    int j = threadIdx.y;          // 0..7
    int tid = j * 49 + p;

    __shared__ __align__(16) float s_in[ICC][52];
    __shared__ __align__(16) float s_w[ICC * 9][OCT + 4];   // row stride 68 floats (16B aligned)

    int oh = p / 7, ow = p - oh * 7;
    int off[9]; float vmsk[9];
#pragma unroll
    for (int kh = 0; kh < 3; kh++)
#pragma unroll
        for (int kw = 0; kw < 3; kw++) {
            int ih = oh + kh - 1, iw = ow + kw - 1;
            int k = kh * 3 + kw;
            bool v = (ih >= 0) && (ih < 7) && (iw >= 0) && (iw < 7);
            vmsk[k] = v ? 1.f : 0.f;
            off[k] = v ? (ih * 7 + iw) : 0;
        }

    unsigned long long acc2[4] = {0ull, 0ull, 0ull, 0ull};
    const float* inN = in + ((size_t)n * IC + ic0) * PIX;

    for (int icb = 0; icb < icn; icb += ICC) {
        __syncthreads();
        {   // input chunk: exactly one element per thread (8*49 = 392)
            int ci = tid / 49, pp = tid - ci * 49;
            s_in[ci][pp] = inN[(size_t)(icb + ci) * PIX + pp];
        }
        // weights: 64*8*9 = 4608 elements; k fastest -> contiguous gmem reads
        for (int t = tid; t < OCT * ICC * 9; t += 392) {
            int ocl = t / (ICC * 9);
            int rem = t - ocl * (ICC * 9);      // = ci*9 + k
            s_w[rem][ocl] = wt[((size_t)(ocbase + ocl) * wstride + ic0 + icb) * 9 + rem];
        }
        __syncthreads();
#pragma unroll
        for (int ci = 0; ci < ICC; ci++) {
            float v[9];
#pragma unroll
            for (int k = 0; k < 9; k++) v[k] = s_in[ci][off[k]] * vmsk[k];
#pragma unroll
            for (int k = 0; k < 9; k++) {
                unsigned long long vv = pack2(v[k]);
                const ulonglong2* wr = (const ulonglong2*)&s_w[ci * 9 + k][j * 8];
                ulonglong2 wA = wr[0];
                ulonglong2 wB = wr[1];
                fma2(acc2[0], vv, wA.x);
                fma2(acc2[1], vv, wA.y);
                fma2(acc2[2], vv, wB.x);
                fma2(acc2[3], vv, wB.y);
            }
        }
    }

    float accf[8];
#pragma unroll
    for (int q = 0; q < 4; q++) { float2 f = unpack2(acc2[q]); accf[2 * q] = f.x; accf[2 * q + 1] = f.y; }

#pragma unroll
    for (int r = 0; r < 8; r++) {
        int oc = ocbase + j * 8 + r;
        float val = accf[r];
        if (nsplit == 1) {
            if (postop == 1) {
                float gg = bn[oc], bb = bn[OC + oc], mm = bn[2 * OC + oc], vv = bn[3 * OC + oc];
                val = (val - mm) * gg * rsqrtf(vv + 1e-5f) + bb;
                val = fmaxf(val, 0.f);
            }
            out[((size_t)n * OC + oc) * PIX + p] = val;
        } else {
            out[((size_t)(ks * N + n) * OC + oc) * PIX + p] = val;
        }
    }
}

// sum ksplit partials, optional BN+ReLU
__global__ void finish_k(const float* __restrict__ part, int nsplit, int chunk,
                         const float* __restrict__ bn, float* __restrict__ out,
                         int OC, int total, int postop)
{
    int i = blockIdx.x * blockDim.x + threadIdx.x;
    if (i >= total) return;
    float s = 0.f;
    for (int ks = 0; ks < nsplit; ks++) s += part[(size_t)ks * chunk + i];
    if (postop == 1) {
        int oc = (i / PIX) % OC;
        float g = bn[oc], b = bn[OC + oc], m = bn[2 * OC + oc], v = bn[3 * OC + oc];
        s = (s - m) * g * rsqrtf(v + 1e-5f) + b;
        s = fmaxf(s, 0.f);
    }
    out[i] = s;
}

// ===================== small kernels =====================
__global__ void transpose_k(const float* __restrict__ x, float* __restrict__ xt) {
    int i = blockIdx.x * blockDim.x + threadIdx.x;
    const int total = NBT * 2048 * PIX;
    if (i >= total) return;
    int p = i % PIX;
    int c = (i / PIX) % 2048;
    int bt = i / (PIX * 2048);
    int b = bt / TSEG, t = bt - b * TSEG;
    xt[i] = x[(((size_t)b * 2048 + c) * TSEG + t) * PIX + p];
}

__global__ void mask_final_k(const float* __restrict__ y2, const float* __restrict__ w3,
                             float* __restrict__ mask, float* __restrict__ outmask)
{
    int n = blockIdx.x;
    int p = threadIdx.x, g = threadIdx.y;
    int oh = p / 7, ow = p - oh * 7;
    float s = 0.f;
    for (int ic = g; ic < 512; ic += 8) {
        const float* row = y2 + ((size_t)n * 512 + ic) * PIX;
        const float* wr = w3 + ic * 9;
#pragma unroll
        for (int kh = 0; kh < 3; kh++)
#pragma unroll
            for (int kw = 0; kw < 3; kw++) {
                int ih = oh + kh - 1, iw = ow + kw - 1;
                if (ih >= 0 && ih < 7 && iw >= 0 && iw < 7)
                    s += row[ih * 7 + iw] * wr[kh * 3 + kw];
            }
    }
    __shared__ float red[8][49];
    red[g][p] = s;
    __syncthreads();
    if (g == 0) {
        float tot = 0.f;
#pragma unroll
        for (int q = 0; q < 8; q++) tot += red[q][p];
        float m = 1.f / (1.f + expf(-tot));
        mask[n * PIX + p] = m;
        outmask[n * PIX + p] = m;
    }
}

__global__ void mx_k(const float* __restrict__ xt, const float* __restrict__ mask, float* __restrict__ mx) {
    int i = blockIdx.x * blockDim.x + threadIdx.x;
    const int total = NBT * 2048 * PIX;
    if (i >= total) return;
    int p = i % PIX;
    int bt = i / (PIX * 2048);
    mx[i] = xt[i] * mask[bt * PIX + p];
}

__global__ void meanx_k(const float* __restrict__ mx, float* __restrict__ meanx) {
    int i = blockIdx.x * blockDim.x + threadIdx.x;
    const int inner = 2048 * PIX;
    if (i >= 2 * inner) return;
    int b = i / inner, r = i - b * inner;
    float s = 0.f;
    for (int t = 0; t < TSEG; t++) s += mx[((size_t)(b * TSEG + t)) * inner + r];
    meanx[i] = s * (1.f / (float)TSEG);
}

__global__ void mxc_k(const float* __restrict__ mx, float* __restrict__ mxc) {
    int i = blockIdx.x * blockDim.x + threadIdx.x;
    if (i >= NBT * 2048) return;
    const float* row = mx + (size_t)i * PIX;
    float s = 0.f;
    for (int p = 0; p < PIX; p++) s += row[p];
    mxc[i] = s * (1.f / (float)PIX);
}

__global__ void attfea_k(const float* __restrict__ mxc, const float* __restrict__ wf,
                         float* __restrict__ attfea)
{
    int bt = blockIdx.x;
    int tid = threadIdx.x;
    __shared__ float sr[256];
    float s = 0.f;
    for (int c = tid; c < 2048; c += 256) s += mxc[bt * 2048 + c] * wf[c];
    sr[tid] = s;
    __syncthreads();
    for (int st = 128; st > 0; st >>= 1) {
        if (tid < st) sr[tid] += sr[tid + st];
        __syncthreads();
    }
    if (tid == 0) attfea[bt] = sr[0];
}

// softmax over t per batch row; aw is constant across all steps (shift invariance)
__global__ void aw_k(const float* __restrict__ attfea, float* __restrict__ aw,
                     float* __restrict__ out_aws)
{
    int b = threadIdx.x;
    if (b >= 2) return;
    float m = -1e30f;
    for (int t = 0; t < TSEG; t++) m = fmaxf(m, attfea[b * TSEG + t]);
    float sum = 0.f;
    for (int t = 0; t < TSEG; t++) sum += expf(attfea[b * TSEG + t] - m);
    for (int t = 0; t < TSEG; t++) {
        float a = expf(attfea[b * TSEG + t] - m) / sum;
        aw[b * TSEG + t] = a;
        out_aws[b * TSEG + t] = a;
    }
}

// gates0[b][oc][p] = lstm_b[oc] + sum_t aw[b][t]*Gx[bt][oc][p]
__global__ void ginit_k(const float* __restrict__ Gx, const float* __restrict__ aw,
                        const float* __restrict__ lstm_b, float* __restrict__ gates0)
{
    int i = blockIdx.x * blockDim.x + threadIdx.x;
    const int total = 2 * 2048 * PIX;
    if (i >= total) return;
    int p = i % PIX;
    int oc = (i / PIX) % 2048;
    int b = i / (PIX * 2048);
    float s = lstm_b[oc];
    for (int t = 0; t < TSEG; t++)
        s += aw[b * TSEG + t] * Gx[(((size_t)(b * TSEG + t)) * 2048 + oc) * PIX + p];
    gates0[i] = s;
}

// pointwise LSTM update + per-channel spatial mean; block (49,8), grid (2,64)
__global__ void lstm_point_k(const float* __restrict__ gates0, const float* __restrict__ part,
                             float* __restrict__ h, float* __restrict__ cst,
                             float* __restrict__ houts, int t)
{
    int b = blockIdx.x;
    int c = blockIdx.y * 8 + threadIdx.y;
    int p = threadIdx.x;
    size_t base = ((size_t)b * 2048) * PIX + p;
    float gi = gates0[base + (size_t)c * PIX];
    float gf = gates0[base + (size_t)(512 + c) * PIX];
    float go = gates0[base + (size_t)(1024 + c) * PIX];
    float gg = gates0[base + (size_t)(1536 + c) * PIX];
#pragma unroll
    for (int ks = 0; ks < 4; ks++) {
        size_t pb = ((size_t)(ks * 2 + b) * 2048) * PIX + p;
        gi += part[pb + (size_t)c * PIX];
        gf += part[pb + (size_t)(512 + c) * PIX];
        go += part[pb + (size_t)(1024 + c) * PIX];
        gg += part[pb + (size_t)(1536 + c) * PIX];
    }
    size_t hidx = ((size_t)b * 512 + c) * PIX + p;
    float cprev = cst[hidx];
    float si = 1.f / (1.f + expf(-gi));
    float sf = 1.f / (1.f + expf(-gf));
    float so = 1.f / (1.f + expf(-go));
    float c2 = sf * cprev + si * tanhf(gg);
    float h2 = so * tanhf(c2);
    cst[hidx] = c2;
    h[hidx] = h2;
    __shared__ float red[8][49];
    red[threadIdx.y][p] = h2;
    __syncthreads();
    if (p == 0) {
        float s = 0.f;
        for (int q = 0; q < 49; q++) s += red[threadIdx.y][q];
        houts[((size_t)t * 2 + b) * 512 + c] = s * (1.f / (float)PIX);
    }
}

__global__ void final_k(const float* __restrict__ houts, const float* __restrict__ fc_w,
                        const float* __restrict__ fc_b, float* __restrict__ out)
{
    __shared__ float om[1024];
    int tid = threadIdx.x;
    for (int i = tid; i < 1024; i += 512) {
        int b = i / 512, c = i - b * 512;
        float s = 0.f;
        for (int t = 0; t < TSEG; t++) s += houts[((size_t)t * 2 + b) * 512 + c];
        om[i] = s * (1.f / (float)TSEG);
    }
    __syncthreads();
    for (int i = tid; i < 202; i += 512) {
        int b = i / 101, k = i - b * 101;
        float s = fc_b[k];
        for (int c = 0; c < 512; c++) s += om[b * 512 + c] * fc_w[k * 512 + c];
        out[i] = s;
    }
    if (tid == 0) { out[2402] = 0.f; out[2403] = 0.f; }
}

// ===================== host orchestration =====================
static float* symaddr(const void* sym) {
    void* p = nullptr;
    cudaGetSymbolAddress(&p, sym);
    return (float*)p;
}

extern "C" void kernel_launch(void* const* d_in, const int* in_sizes, int n_in,
                              void* d_out, int out_size)
{
    const float* x      = (const float*)d_in[0];
    const float* wf     = (const float*)d_in[1];
    // wh = d_in[2] is mathematically dead (softmax shift invariance)
    const float* fc_w   = (const float*)d_in[3];
    const float* fc_b   = (const float*)d_in[4];
    const float* h0_w1  = (const float*)d_in[5];
    const float* h0_bn1 = (const float*)d_in[6];
    const float* h0_w2  = (const float*)d_in[7];
    const float* h0_bn2 = (const float*)d_in[8];
    const float* c0_w1  = (const float*)d_in[9];
    const float* c0_bn1 = (const float*)d_in[10];
    const float* c0_w2  = (const float*)d_in[11];
    const float* c0_bn2 = (const float*)d_in[12];
    const float* mk_w1  = (const float*)d_in[13];
    const float* mk_bn1 = (const float*)d_in[14];
    const float* mk_w2  = (const float*)d_in[15];
    const float* mk_bn2 = (const float*)d_in[16];
    const float* mk_w3  = (const float*)d_in[17];
    const float* lstm_w = (const float*)d_in[18];
    const float* lstm_b = (const float*)d_in[19];
    float* out = (float*)d_out;

    float* xt     = symaddr(g_xt);
    float* mx     = symaddr(g_mx);
    float* Gx     = symaddr(g_Gx);
    float* y1     = symaddr(g_y1);
    float* y2     = symaddr(g_y2);
    float* mask   = symaddr(g_mask);
    float* meanx  = symaddr(g_meanx);
    float* mxc    = symaddr(g_mxc);
    float* attfea = symaddr(g_attfea);
    float* aw     = symaddr(g_aw);
    float* tmp1   = symaddr(g_tmp1);
    float* h      = symaddr(g_h);
    float* cst    = symaddr(g_cst);
    float* gates0 = symaddr(g_gates0);
    float* part   = symaddr(g_part);
    float* houts  = symaddr(g_houts);

    dim3 cb(49, 8);
    const int ETOT = NBT * 2048 * PIX;

    // ---- mask path ----
    transpose_k<<<(ETOT + 255) / 256, 256>>>(x, xt);
    conv3x3_k<<<dim3(NBT, 16, 1), cb>>>(xt, mk_w1, mk_bn1, y1, 2048, 1024, 2048, 1, 1);
    conv3x3_k<<<dim3(NBT, 8, 1), cb>>>(y1, mk_w2, mk_bn2, y2, 1024, 512, 1024, 1, 1);
    mask_final_k<<<NBT, cb>>>(y2, mk_w3, mask, out + 246);   // mask region of output

    // ---- masked features, reductions, attention (constant over steps) ----
    mx_k<<<(ETOT + 255) / 256, 256>>>(xt, mask, mx);
    meanx_k<<<(2 * 2048 * PIX + 255) / 256, 256>>>(mx, meanx);
    mxc_k<<<(NBT * 2048 + 255) / 256, 256>>>(mx, mxc);
    attfea_k<<<NBT, 256>>>(mxc, wf, attfea);
    aw_k<<<1, 32>>>(attfea, aw, out + 202);                  // aws[-1] region of output

    // ---- Gx = conv_x(mx_t) with lstm_w[:, :2048] (hoisted out of the recurrence) ----
    conv3x3_k<<<dim3(NBT, 32, 1), cb>>>(mx, lstm_w, nullptr, Gx, 2048, 2048, 2560, 1, 0);

    // ---- h0 / c0 init (k-split for parallelism, deterministic partials) ----
    conv3x3_k<<<dim3(2, 16, 8), cb>>>(meanx, h0_w1, nullptr, part, 2048, 1024, 2048, 8, 0);
    finish_k<<<(2 * 1024 * PIX + 255) / 256, 256>>>(part, 8, 2 * 1024 * PIX, h0_bn1, tmp1, 1024, 2 * 1024 * PIX, 1);
    conv3x3_k<<<dim3(2, 8, 8), cb>>>(tmp1, h0_w2, nullptr, part, 1024, 512, 1024, 8, 0);
    finish_k<<<(2 * 512 * PIX + 255) / 256, 256>>>(part, 8, 2 * 512 * PIX, h0_bn2, h, 512, 2 * 512 * PIX, 1);

    conv3x3_k<<<dim3(2, 16, 8), cb>>>(meanx, c0_w1, nullptr, part, 2048, 1024, 2048, 8, 0);
    finish_k<<<(2 * 1024 * PIX + 255) / 256, 256>>>(part, 8, 2 * 1024 * PIX, c0_bn1, tmp1, 1024, 2 * 1024 * PIX, 1);
    conv3x3_k<<<dim3(2, 8, 8), cb>>>(tmp1, c0_w2, nullptr, part, 1024, 512, 1024, 8, 0);
    finish_k<<<(2 * 512 * PIX + 255) / 256, 256>>>(part, 8, 2 * 512 * PIX, c0_bn2, cst, 512, 2 * 512 * PIX, 1);

    // ---- constant part of gates: bias + sum_t aw[t]*Gx[t] ----
    ginit_k<<<(2 * 2048 * PIX + 255) / 256, 256>>>(Gx, aw, lstm_b, gates0);

    // ---- recurrence: only conv_h(h) (512ch) is sequential ----
    for (int t = 0; t < TSEG; t++) {
        conv3x3_k<<<dim3(2, 32, 4), cb>>>(h, lstm_w + (size_t)2048 * 9, nullptr, part,
                                          512, 2048, 2560, 4, 0);
        lstm_point_k<<<dim3(2, 64), cb>>>(gates0, part, h, cst, houts, t);
    }

    // ---- final mean over steps + FC, plus zero losses ----
    final_k<<<1, 512>>>(houts, fc_w, fc_b, out);
}